// round 2
// baseline (speedup 1.0000x reference)
#include <cuda_runtime.h>
#include <cuda_fp16.h>
#include <cstdint>

// Problem constants
#define D_Z     1024
#define D_MODEL 4096
#define M_ROWS  16384          // 8 * 2048
#define EPS     1e-5f

// GEMM tiling
#define BM 128
#define BN 128
#define BK 32
#define LDA 40                 // 32 + 8 pad (fp16 elems) -> conflict-free ldmatrix
#define LDB 136                // 128 + 8 pad

// Scratch (allocation-free rule: device globals)
__device__ __half g_zn[(size_t)M_ROWS * D_Z];     // 32 MB normalized rows, fp16
__device__ __half g_wb[(size_t)D_Z * D_MODEL];    // 8 MB W in fp16

// ---------------------------------------------------------------------------
// Kernel 1: W fp32 -> fp16
// ---------------------------------------------------------------------------
__global__ void wconv_kernel(const float* __restrict__ W) {
    size_t i = (size_t)blockIdx.x * blockDim.x + threadIdx.x;   // one float4 each
    float4 v = ((const float4*)W)[i];
    __half2 p0 = __floats2half2_rn(v.x, v.y);
    __half2 p1 = __floats2half2_rn(v.z, v.w);
    __half2* dst = (__half2*)g_wb;
    dst[i * 2 + 0] = p0;
    dst[i * 2 + 1] = p1;
}

// ---------------------------------------------------------------------------
// Kernel 2: row LayerNorm -> fp16
// ---------------------------------------------------------------------------
__global__ __launch_bounds__(256) void ln_kernel(const float* __restrict__ z,
                                                 const float* __restrict__ gamma,
                                                 const float* __restrict__ beta) {
    int row  = blockIdx.x;
    int t    = threadIdx.x;
    int lane = t & 31;
    int wid  = t >> 5;

    const float4* zp = (const float4*)(z + (size_t)row * D_Z);
    float4 v = zp[t];                       // 256 threads * 4 = 1024

    float s  = v.x + v.y + v.z + v.w;
    float ss = v.x * v.x + v.y * v.y + v.z * v.z + v.w * v.w;
    #pragma unroll
    for (int o = 16; o > 0; o >>= 1) {
        s  += __shfl_xor_sync(0xffffffffu, s, o);
        ss += __shfl_xor_sync(0xffffffffu, ss, o);
    }

    __shared__ float sbuf[8], ssbuf[8];
    __shared__ float smu, srstd;
    if (lane == 0) { sbuf[wid] = s; ssbuf[wid] = ss; }
    __syncthreads();
    if (t == 0) {
        float S = 0.f, SS = 0.f;
        #pragma unroll
        for (int i = 0; i < 8; i++) { S += sbuf[i]; SS += ssbuf[i]; }
        float mu  = S * (1.0f / D_Z);
        float var = SS * (1.0f / D_Z) - mu * mu;
        smu   = mu;
        srstd = rsqrtf(var + EPS);
    }
    __syncthreads();
    float mu = smu, rstd = srstd;

    float4 g = ((const float4*)gamma)[t];
    float4 b = ((const float4*)beta)[t];

    float o0 = (v.x - mu) * rstd * g.x + b.x;
    float o1 = (v.y - mu) * rstd * g.y + b.y;
    float o2 = (v.z - mu) * rstd * g.z + b.z;
    float o3 = (v.w - mu) * rstd * g.w + b.w;

    __half2* dst = (__half2*)(g_zn + (size_t)row * D_Z);
    dst[t * 2 + 0] = __floats2half2_rn(o0, o1);
    dst[t * 2 + 1] = __floats2half2_rn(o2, o3);
}

// ---------------------------------------------------------------------------
// mma / ldmatrix wrappers
// ---------------------------------------------------------------------------
__device__ __forceinline__ void ldmatrix_x4(uint32_t r[4], uint32_t addr) {
    asm volatile("ldmatrix.sync.aligned.m8n8.x4.shared.b16 {%0,%1,%2,%3}, [%4];\n"
                 : "=r"(r[0]), "=r"(r[1]), "=r"(r[2]), "=r"(r[3])
                 : "r"(addr));
}
__device__ __forceinline__ void ldmatrix_x4_trans(uint32_t r[4], uint32_t addr) {
    asm volatile("ldmatrix.sync.aligned.m8n8.x4.trans.shared.b16 {%0,%1,%2,%3}, [%4];\n"
                 : "=r"(r[0]), "=r"(r[1]), "=r"(r[2]), "=r"(r[3])
                 : "r"(addr));
}
__device__ __forceinline__ void mma_16816(float c[4], const uint32_t a[4], const uint32_t b[2]) {
    asm volatile("mma.sync.aligned.m16n8k16.row.col.f32.f16.f16.f32 "
                 "{%0,%1,%2,%3}, {%4,%5,%6,%7}, {%8,%9}, {%0,%1,%2,%3};\n"
                 : "+f"(c[0]), "+f"(c[1]), "+f"(c[2]), "+f"(c[3])
                 : "r"(a[0]), "r"(a[1]), "r"(a[2]), "r"(a[3]),
                   "r"(b[0]), "r"(b[1]));
}

// ---------------------------------------------------------------------------
// Kernel 3: GEMM zn[M,K] @ W[K,N] + bias, scale, 3*tanh(x/3)
// 8 warps = 2(m) x 4(n); warp tile 64x32; per-warp 4x4 mma tiles of 16x8.
// ---------------------------------------------------------------------------
__global__ __launch_bounds__(256) void gemm_kernel(const float* __restrict__ bias,
                                                   const float* __restrict__ scale,
                                                   float* __restrict__ out) {
    __shared__ __align__(16) __half As[BM * LDA];
    __shared__ __align__(16) __half Bs[BK * LDB];

    int tid  = threadIdx.x;
    int wid  = tid >> 5;
    int lane = tid & 31;
    int wm   = wid >> 2;        // 0..1 (64 rows each)
    int wn   = wid & 3;         // 0..3 (32 cols each)
    int bm   = blockIdx.y;
    int bn   = blockIdx.x;

    float acc[4][4][4];
    #pragma unroll
    for (int i = 0; i < 4; i++)
        #pragma unroll
        for (int j = 0; j < 4; j++)
            #pragma unroll
            for (int k = 0; k < 4; k++) acc[i][j][k] = 0.f;

    const __half* Ag = g_zn + (size_t)(bm * BM) * D_Z;
    const __half* Bg = g_wb + (size_t)(bn * BN);

    uint32_t as_base = (uint32_t)__cvta_generic_to_shared(As);
    uint32_t bs_base = (uint32_t)__cvta_generic_to_shared(Bs);

    int r8 = lane & 7;
    int q  = lane >> 3;

    for (int kt = 0; kt < D_Z; kt += BK) {
        // ---- load A tile: 128 rows x 32 cols (512 x 16B chunks, 2/thread)
        #pragma unroll
        for (int c = 0; c < 2; c++) {
            int chunk = tid + c * 256;
            int row   = chunk >> 2;
            int col8  = (chunk & 3) * 8;
            uint4 v = *(const uint4*)(Ag + (size_t)row * D_Z + kt + col8);
            *(uint4*)(As + row * LDA + col8) = v;
        }
        // ---- load B tile: 32 rows x 128 cols
        #pragma unroll
        for (int c = 0; c < 2; c++) {
            int chunk = tid + c * 256;
            int row   = chunk >> 4;
            int col8  = (chunk & 15) * 8;
            uint4 v = *(const uint4*)(Bg + (size_t)(kt + row) * D_MODEL + col8);
            *(uint4*)(Bs + row * LDB + col8) = v;
        }
        __syncthreads();

        #pragma unroll
        for (int ks = 0; ks < 2; ks++) {
            int ko = ks * 16;

            uint32_t af[4][4];
            #pragma unroll
            for (int mi = 0; mi < 4; mi++) {
                int arow = wm * 64 + mi * 16 + r8 + (q & 1) * 8;
                int acol = ko + (q >> 1) * 8;
                ldmatrix_x4(af[mi], as_base + (uint32_t)(arow * LDA + acol) * 2);
            }

            uint32_t bfr[4][2];
            #pragma unroll
            for (int ni = 0; ni < 2; ni++) {
                int brow = ko + (q & 1) * 8 + r8;
                int bcol = wn * 32 + ni * 16 + (q >> 1) * 8;
                uint32_t t4[4];
                ldmatrix_x4_trans(t4, bs_base + (uint32_t)(brow * LDB + bcol) * 2);
                bfr[ni * 2 + 0][0] = t4[0]; bfr[ni * 2 + 0][1] = t4[1];
                bfr[ni * 2 + 1][0] = t4[2]; bfr[ni * 2 + 1][1] = t4[3];
            }

            #pragma unroll
            for (int mi = 0; mi < 4; mi++)
                #pragma unroll
                for (int nb = 0; nb < 4; nb++)
                    mma_16816(acc[mi][nb], af[mi], bfr[nb]);
        }
        __syncthreads();
    }

    // ---- epilogue: x = (acc + b) * scale ; out = 3 * tanh(x / 3)
    float inv = scale[0] * (1.0f / 3.0f);
    int rr = lane >> 2;
    int cq = (lane & 3) * 2;

    #pragma unroll
    for (int nb = 0; nb < 4; nb++) {
        int col = bn * BN + wn * 32 + nb * 8 + cq;
        float b0 = bias[col];
        float b1 = bias[col + 1];
        #pragma unroll
        for (int mi = 0; mi < 4; mi++) {
            int row = bm * BM + wm * 64 + mi * 16 + rr;
            float* o0 = out + (size_t)row * D_MODEL + col;
            float* o1 = out + (size_t)(row + 8) * D_MODEL + col;
            o0[0] = 3.0f * tanhf((acc[mi][nb][0] + b0) * inv);
            o0[1] = 3.0f * tanhf((acc[mi][nb][1] + b1) * inv);
            o1[0] = 3.0f * tanhf((acc[mi][nb][2] + b0) * inv);
            o1[1] = 3.0f * tanhf((acc[mi][nb][3] + b1) * inv);
        }
    }
}

// ---------------------------------------------------------------------------
// launch
// ---------------------------------------------------------------------------
extern "C" void kernel_launch(void* const* d_in, const int* in_sizes, int n_in,
                              void* d_out, int out_size) {
    const float* z     = (const float*)d_in[0];   // [8,2048,1024]
    const float* gamma = (const float*)d_in[1];   // [1024]
    const float* beta  = (const float*)d_in[2];   // [1024]
    const float* W     = (const float*)d_in[3];   // [1024,4096]
    const float* b     = (const float*)d_in[4];   // [4096]
    const float* scale = (const float*)d_in[5];   // [1]
    float* out = (float*)d_out;                   // [8,2048,4096]

    (void)in_sizes; (void)n_in; (void)out_size;

    // W -> fp16 : 1048576 float4s
    wconv_kernel<<<4096, 256>>>(W);
    // LayerNorm: one block per row
    ln_kernel<<<M_ROWS, 256>>>(z, gamma, beta);
    // GEMM + epilogue
    dim3 grid(D_MODEL / BN, M_ROWS / BM);   // (32, 128)
    gemm_kernel<<<grid, 256>>>(b, scale, out);
}

// round 4
// speedup vs baseline: 1.1478x; 1.1478x over previous
#include <cuda_runtime.h>
#include <cuda_fp16.h>
#include <cstdint>

// ---------------------------------------------------------------- constants
#define D_Z     1024
#define D_MODEL 4096
#define M_ROWS  16384
#define EPS     1e-5f

#define BM 128
#define BN 256
#define BK 32
#define KITERS (D_Z / BK)      // 32
#define STAGES 4

#define LDA 40                  // 32 + 8 pad (fp16), row pitch 80B (16B-aligned)
#define LDB 264                 // 256 + 8 pad, row pitch 528B (16B-aligned)
#define A_STAGE_B (BM * LDA * 2)          // 10240 B
#define B_STAGE_B (BK * LDB * 2)          // 16896 B
#define STAGE_B   (A_STAGE_B + B_STAGE_B) // 27136 B
#define SMEM_TOTAL (STAGES * STAGE_B)     // 108544 B

// scratch (allocation-free rule: device globals)
__device__ __half g_zn[(size_t)M_ROWS * D_Z];     // LN output fp16 [M,K]
__device__ __half g_wb[(size_t)D_Z * D_MODEL];    // W fp16 [K,N]

// ---------------------------------------------------------------- K1: W fp32 -> fp16
__global__ void wconv_kernel(const float* __restrict__ W) {
    size_t i = (size_t)blockIdx.x * blockDim.x + threadIdx.x;
    float4 v = ((const float4*)W)[i];
    __half2* dst = (__half2*)g_wb;
    dst[i * 2 + 0] = __floats2half2_rn(v.x, v.y);
    dst[i * 2 + 1] = __floats2half2_rn(v.z, v.w);
}

// ---------------------------------------------------------------- K2: LayerNorm -> fp16
__global__ __launch_bounds__(256) void ln_kernel(const float* __restrict__ z,
                                                 const float* __restrict__ gamma,
                                                 const float* __restrict__ beta) {
    int row = blockIdx.x, t = threadIdx.x, lane = t & 31, wid = t >> 5;
    const float4* zp = (const float4*)(z + (size_t)row * D_Z);
    float4 v = zp[t];

    float s  = v.x + v.y + v.z + v.w;
    float ss = v.x * v.x + v.y * v.y + v.z * v.z + v.w * v.w;
    #pragma unroll
    for (int o = 16; o > 0; o >>= 1) {
        s  += __shfl_xor_sync(0xffffffffu, s, o);
        ss += __shfl_xor_sync(0xffffffffu, ss, o);
    }
    __shared__ float sbuf[8], ssbuf[8], smu, srstd;
    if (lane == 0) { sbuf[wid] = s; ssbuf[wid] = ss; }
    __syncthreads();
    if (t == 0) {
        float S = 0.f, SS = 0.f;
        #pragma unroll
        for (int i = 0; i < 8; i++) { S += sbuf[i]; SS += ssbuf[i]; }
        float mu  = S * (1.0f / D_Z);
        float var = SS * (1.0f / D_Z) - mu * mu;
        smu = mu; srstd = rsqrtf(var + EPS);
    }
    __syncthreads();
    float mu = smu, rstd = srstd;

    float4 g = ((const float4*)gamma)[t];
    float4 b = ((const float4*)beta)[t];
    float o0 = (v.x - mu) * rstd * g.x + b.x;
    float o1 = (v.y - mu) * rstd * g.y + b.y;
    float o2 = (v.z - mu) * rstd * g.z + b.z;
    float o3 = (v.w - mu) * rstd * g.w + b.w;

    __half2* dst = (__half2*)(g_zn + (size_t)row * D_Z);
    dst[t * 2 + 0] = __floats2half2_rn(o0, o1);
    dst[t * 2 + 1] = __floats2half2_rn(o2, o3);
}

// ---------------------------------------------------------------- PTX wrappers
__device__ __forceinline__ void ldmatrix_x4(uint32_t r[4], uint32_t addr) {
    asm volatile("ldmatrix.sync.aligned.m8n8.x4.shared.b16 {%0,%1,%2,%3}, [%4];\n"
                 : "=r"(r[0]), "=r"(r[1]), "=r"(r[2]), "=r"(r[3]) : "r"(addr));
}
__device__ __forceinline__ void ldmatrix_x4_trans(uint32_t r[4], uint32_t addr) {
    asm volatile("ldmatrix.sync.aligned.m8n8.x4.trans.shared.b16 {%0,%1,%2,%3}, [%4];\n"
                 : "=r"(r[0]), "=r"(r[1]), "=r"(r[2]), "=r"(r[3]) : "r"(addr));
}
__device__ __forceinline__ void mma_16816(float c[4], const uint32_t a[4], const uint32_t b[2]) {
    asm volatile("mma.sync.aligned.m16n8k16.row.col.f32.f16.f16.f32 "
                 "{%0,%1,%2,%3}, {%4,%5,%6,%7}, {%8,%9}, {%0,%1,%2,%3};\n"
                 : "+f"(c[0]), "+f"(c[1]), "+f"(c[2]), "+f"(c[3])
                 : "r"(a[0]), "r"(a[1]), "r"(a[2]), "r"(a[3]), "r"(b[0]), "r"(b[1]));
}
__device__ __forceinline__ void cp_async16(uint32_t dst, const void* src) {
    asm volatile("cp.async.cg.shared.global [%0], [%1], 16;\n" :: "r"(dst), "l"(src) : "memory");
}
#define CP_COMMIT() asm volatile("cp.async.commit_group;" ::: "memory")
#define CP_WAIT2()  asm volatile("cp.async.wait_group %0;" :: "n"(STAGES - 2) : "memory")

// accurate-ish fast tanh: tanh(t) = 1 - 2/(exp(2t)+1), rel err ~1e-6
__device__ __forceinline__ float fast_tanh3(float x, float sc3) {
    float t = x * sc3;                    // x*scale/3
    float e;
    asm("ex2.approx.f32 %0, %1;" : "=f"(e) : "f"(t * 2.885390082f));   // exp(2t)
    float r;
    asm("rcp.approx.f32 %0, %1;" : "=f"(r) : "f"(e + 1.0f));
    return 3.0f * (1.0f - 2.0f * r);
}

// ---------------------------------------------------------------- K3: pipelined HMMA GEMM
__device__ __forceinline__ void load_stage(uint32_t sb, int slot, int kt, int bm, int bn, int tid) {
    uint32_t abase = sb + slot * STAGE_B;
    uint32_t bbase = abase + A_STAGE_B;
    // A: 128 rows x 32 f16 = 512 x 16B chunks, 2/thread
    const char* Ag = (const char*)(g_zn + (size_t)(bm * BM) * D_Z + kt * BK);
    #pragma unroll
    for (int i = 0; i < 2; i++) {
        int chunk = tid + i * 256;
        int row = chunk >> 2, c = chunk & 3;
        cp_async16(abase + (uint32_t)(row * LDA + c * 8) * 2,
                   Ag + (size_t)row * (D_Z * 2) + c * 16);
    }
    // B: 32 rows x 256 f16 = 1024 x 16B chunks, 4/thread
    const char* Bg = (const char*)(g_wb + (size_t)(kt * BK) * D_MODEL + bn * BN);
    #pragma unroll
    for (int i = 0; i < 4; i++) {
        int chunk = tid + i * 256;
        int row = chunk >> 5, c = chunk & 31;
        cp_async16(bbase + (uint32_t)(row * LDB + c * 8) * 2,
                   Bg + (size_t)row * (D_MODEL * 2) + c * 16);
    }
}

__global__ __launch_bounds__(256, 1) void gemm_kernel(const float* __restrict__ bias,
                                                      const float* __restrict__ scale,
                                                      float* __restrict__ out) {
    extern __shared__ __align__(16) char smem[];
    uint32_t sb;
    asm("{ .reg .u64 t; cvta.to.shared.u64 t, %1; cvt.u32.u64 %0, t; }" : "=r"(sb) : "l"(smem));

    int tid  = threadIdx.x;
    int wid  = tid >> 5;
    int lane = tid & 31;
    int wm   = wid >> 2;        // 0..1  (64 rows)
    int wn   = wid & 3;         // 0..3  (64 cols)
    int bm   = blockIdx.y;
    int bn   = blockIdx.x;

    float acc[4][8][4];
    #pragma unroll
    for (int i = 0; i < 4; i++)
        #pragma unroll
        for (int j = 0; j < 8; j++)
            #pragma unroll
            for (int k = 0; k < 4; k++) acc[i][j][k] = 0.f;

    int r8 = lane & 7;
    int q  = lane >> 3;

    // prologue: fill STAGES-1 slots
    #pragma unroll
    for (int s = 0; s < STAGES - 1; s++) {
        load_stage(sb, s, s, bm, bn, tid);
        CP_COMMIT();
    }

    for (int kt = 0; kt < KITERS; kt++) {
        CP_WAIT2();
        __syncthreads();

        // issue next stage's loads (slot being overwritten was consumed at kt-1)
        if (kt + STAGES - 1 < KITERS)
            load_stage(sb, (kt + STAGES - 1) % STAGES, kt + STAGES - 1, bm, bn, tid);
        CP_COMMIT();

        uint32_t abase = sb + (kt % STAGES) * STAGE_B;
        uint32_t bbase = abase + A_STAGE_B;

        #pragma unroll
        for (int ks = 0; ks < 2; ks++) {
            int ko = ks * 16;

            uint32_t af[4][4];
            #pragma unroll
            for (int mi = 0; mi < 4; mi++) {
                int arow = wm * 64 + mi * 16 + r8 + (q & 1) * 8;
                int acol = ko + (q >> 1) * 8;
                ldmatrix_x4(af[mi], abase + (uint32_t)(arow * LDA + acol) * 2);
            }

            uint32_t bfr[8][2];
            #pragma unroll
            for (int ni = 0; ni < 4; ni++) {
                int brow = ko + (q & 1) * 8 + r8;
                int bcol = wn * 64 + ni * 16 + (q >> 1) * 8;
                uint32_t t4[4];
                ldmatrix_x4_trans(t4, bbase + (uint32_t)(brow * LDB + bcol) * 2);
                bfr[ni * 2 + 0][0] = t4[0]; bfr[ni * 2 + 0][1] = t4[1];
                bfr[ni * 2 + 1][0] = t4[2]; bfr[ni * 2 + 1][1] = t4[3];
            }

            #pragma unroll
            for (int mi = 0; mi < 4; mi++)
                #pragma unroll
                for (int nb = 0; nb < 8; nb++)
                    mma_16816(acc[mi][nb], af[mi], bfr[nb]);
        }
    }

    // epilogue: out = 3*tanh((acc + bias)*scale/3)
    float sc3 = scale[0] * (1.0f / 3.0f);
    int rr = lane >> 2;
    int cq = (lane & 3) * 2;

    #pragma unroll
    for (int nb = 0; nb < 8; nb++) {
        int col = bn * BN + wn * 64 + nb * 8 + cq;
        float2 bv = *(const float2*)(bias + col);
        #pragma unroll
        for (int mi = 0; mi < 4; mi++) {
            int row = bm * BM + wm * 64 + mi * 16 + rr;
            float2 o0, o1;
            o0.x = fast_tanh3(acc[mi][nb][0] + bv.x, sc3);
            o0.y = fast_tanh3(acc[mi][nb][1] + bv.y, sc3);
            o1.x = fast_tanh3(acc[mi][nb][2] + bv.x, sc3);
            o1.y = fast_tanh3(acc[mi][nb][3] + bv.y, sc3);
            *(float2*)(out + (size_t)row * D_MODEL + col)       = o0;
            *(float2*)(out + (size_t)(row + 8) * D_MODEL + col) = o1;
        }
    }
}

// ---------------------------------------------------------------- launch
extern "C" void kernel_launch(void* const* d_in, const int* in_sizes, int n_in,
                              void* d_out, int out_size) {
    const float* z     = (const float*)d_in[0];
    const float* gamma = (const float*)d_in[1];
    const float* beta  = (const float*)d_in[2];
    const float* W     = (const float*)d_in[3];
    const float* b     = (const float*)d_in[4];
    const float* scale = (const float*)d_in[5];
    float* out = (float*)d_out;
    (void)in_sizes; (void)n_in; (void)out_size;

    cudaFuncSetAttribute(gemm_kernel, cudaFuncAttributeMaxDynamicSharedMemorySize, SMEM_TOTAL);

    wconv_kernel<<<4096, 256>>>(W);
    ln_kernel<<<M_ROWS, 256>>>(z, gamma, beta);
    dim3 grid(D_MODEL / BN, M_ROWS / BM);   // (16, 128)
    gemm_kernel<<<grid, 256, SMEM_TOTAL>>>(b, scale, out);
}

// round 5
// speedup vs baseline: 1.1499x; 1.0018x over previous
#include <cuda_runtime.h>
#include <cuda_fp16.h>
#include <cstdint>

// ---------------------------------------------------------------- constants
#define D_Z     1024
#define D_MODEL 4096
#define M_ROWS  16384
#define EPS     1e-5f

#define BM 256
#define BN 128
#define BK 64
#define KITERS (D_Z / BK)      // 16
#define STAGES 3

#define LDA 72                  // 64 + 8 pad (fp16): 144B row pitch, conflict-free
#define LDB 136                 // 128 + 8 pad: 272B row pitch, conflict-free
#define A_STAGE_B (BM * LDA * 2)          // 36864 B
#define B_STAGE_B (BK * LDB * 2)          // 17408 B
#define STAGE_B   (A_STAGE_B + B_STAGE_B) // 54272 B
#define SMEM_TOTAL (STAGES * STAGE_B)     // 162816 B

// scratch (allocation-free rule: device globals)
__device__ __half g_zn[(size_t)M_ROWS * D_Z];     // LN output fp16 [M,K]
__device__ __half g_wb[(size_t)D_Z * D_MODEL];    // W fp16 [K,N]

// ---------------------------------------------------------------- K1: W fp32 -> fp16
__global__ void wconv_kernel(const float* __restrict__ W) {
    size_t i = (size_t)blockIdx.x * blockDim.x + threadIdx.x;
    float4 v = ((const float4*)W)[i];
    __half2* dst = (__half2*)g_wb;
    dst[i * 2 + 0] = __floats2half2_rn(v.x, v.y);
    dst[i * 2 + 1] = __floats2half2_rn(v.z, v.w);
}

// ---------------------------------------------------------------- K2: LayerNorm -> fp16
__global__ __launch_bounds__(256) void ln_kernel(const float* __restrict__ z,
                                                 const float* __restrict__ gamma,
                                                 const float* __restrict__ beta) {
    int row = blockIdx.x, t = threadIdx.x, lane = t & 31, wid = t >> 5;
    const float4* zp = (const float4*)(z + (size_t)row * D_Z);
    float4 v = zp[t];

    float s  = v.x + v.y + v.z + v.w;
    float ss = v.x * v.x + v.y * v.y + v.z * v.z + v.w * v.w;
    #pragma unroll
    for (int o = 16; o > 0; o >>= 1) {
        s  += __shfl_xor_sync(0xffffffffu, s, o);
        ss += __shfl_xor_sync(0xffffffffu, ss, o);
    }
    __shared__ float sbuf[8], ssbuf[8], smu, srstd;
    if (lane == 0) { sbuf[wid] = s; ssbuf[wid] = ss; }
    __syncthreads();
    if (t == 0) {
        float S = 0.f, SS = 0.f;
        #pragma unroll
        for (int i = 0; i < 8; i++) { S += sbuf[i]; SS += ssbuf[i]; }
        float mu  = S * (1.0f / D_Z);
        float var = SS * (1.0f / D_Z) - mu * mu;
        smu = mu; srstd = rsqrtf(var + EPS);
    }
    __syncthreads();
    float mu = smu, rstd = srstd;

    float4 g = ((const float4*)gamma)[t];
    float4 b = ((const float4*)beta)[t];
    float o0 = (v.x - mu) * rstd * g.x + b.x;
    float o1 = (v.y - mu) * rstd * g.y + b.y;
    float o2 = (v.z - mu) * rstd * g.z + b.z;
    float o3 = (v.w - mu) * rstd * g.w + b.w;

    __half2* dst = (__half2*)(g_zn + (size_t)row * D_Z);
    dst[t * 2 + 0] = __floats2half2_rn(o0, o1);
    dst[t * 2 + 1] = __floats2half2_rn(o2, o3);
}

// ---------------------------------------------------------------- PTX wrappers
__device__ __forceinline__ void ldmatrix_x4(uint32_t r[4], uint32_t addr) {
    asm volatile("ldmatrix.sync.aligned.m8n8.x4.shared.b16 {%0,%1,%2,%3}, [%4];\n"
                 : "=r"(r[0]), "=r"(r[1]), "=r"(r[2]), "=r"(r[3]) : "r"(addr));
}
__device__ __forceinline__ void ldmatrix_x4_trans(uint32_t r[4], uint32_t addr) {
    asm volatile("ldmatrix.sync.aligned.m8n8.x4.trans.shared.b16 {%0,%1,%2,%3}, [%4];\n"
                 : "=r"(r[0]), "=r"(r[1]), "=r"(r[2]), "=r"(r[3]) : "r"(addr));
}
__device__ __forceinline__ void mma_16816(float c[4], const uint32_t a[4], const uint32_t b[2]) {
    asm volatile("mma.sync.aligned.m16n8k16.row.col.f32.f16.f16.f32 "
                 "{%0,%1,%2,%3}, {%4,%5,%6,%7}, {%8,%9}, {%0,%1,%2,%3};\n"
                 : "+f"(c[0]), "+f"(c[1]), "+f"(c[2]), "+f"(c[3])
                 : "r"(a[0]), "r"(a[1]), "r"(a[2]), "r"(a[3]), "r"(b[0]), "r"(b[1]));
}
__device__ __forceinline__ void cp_async16(uint32_t dst, const void* src) {
    asm volatile("cp.async.cg.shared.global [%0], [%1], 16;\n" :: "r"(dst), "l"(src) : "memory");
}
#define CP_COMMIT() asm volatile("cp.async.commit_group;" ::: "memory")
#define CP_WAIT1()  asm volatile("cp.async.wait_group 1;" ::: "memory")

// fast tanh: tanh(t) = 1 - 2/(exp(2t)+1), rel err ~1e-6
__device__ __forceinline__ float fast_tanh3(float x, float sc3) {
    float t = x * sc3;
    float e;
    asm("ex2.approx.f32 %0, %1;" : "=f"(e) : "f"(t * 2.885390082f));
    float r;
    asm("rcp.approx.f32 %0, %1;" : "=f"(r) : "f"(e + 1.0f));
    return 3.0f * (1.0f - 2.0f * r);
}

// ---------------------------------------------------------------- K3: pipelined HMMA GEMM
__device__ __forceinline__ void load_stage(uint32_t sb, int slot, int kt, int bm, int bn, int tid) {
    uint32_t abase = sb + slot * STAGE_B;
    uint32_t bbase = abase + A_STAGE_B;
    // A: 256 rows x 64 f16 = 2048 x 16B chunks, 4/thread
    const char* Ag = (const char*)(g_zn + (size_t)(bm * BM) * D_Z + kt * BK);
    #pragma unroll
    for (int i = 0; i < 4; i++) {
        int chunk = tid + i * 512;
        int row = chunk >> 3, c = chunk & 7;
        cp_async16(abase + (uint32_t)(row * LDA + c * 8) * 2,
                   Ag + (size_t)row * (D_Z * 2) + c * 16);
    }
    // B: 64 rows x 128 f16 = 1024 x 16B chunks, 2/thread
    const char* Bg = (const char*)(g_wb + (size_t)(kt * BK) * D_MODEL + bn * BN);
    #pragma unroll
    for (int i = 0; i < 2; i++) {
        int chunk = tid + i * 512;
        int row = chunk >> 4, c = chunk & 15;
        cp_async16(bbase + (uint32_t)(row * LDB + c * 8) * 2,
                   Bg + (size_t)row * (D_MODEL * 2) + c * 16);
    }
}

__global__ __launch_bounds__(512, 1) void gemm_kernel(const float* __restrict__ bias,
                                                      const float* __restrict__ scale,
                                                      float* __restrict__ out) {
    extern __shared__ __align__(16) char smem[];
    uint32_t sb;
    asm("{ .reg .u64 t; cvta.to.shared.u64 t, %1; cvt.u32.u64 %0, t; }" : "=r"(sb) : "l"(smem));

    int tid  = threadIdx.x;
    int wid  = tid >> 5;
    int lane = tid & 31;
    int wm   = wid >> 2;        // 0..3 (64 rows)
    int wn   = wid & 3;         // 0..3 (32 cols)
    int bm   = blockIdx.y;
    int bn   = blockIdx.x;

    float acc[4][4][4];
    #pragma unroll
    for (int i = 0; i < 4; i++)
        #pragma unroll
        for (int j = 0; j < 4; j++)
            #pragma unroll
            for (int k = 0; k < 4; k++) acc[i][j][k] = 0.f;

    int r8 = lane & 7;
    int q  = lane >> 3;

    // prologue: fill 2 slots
    load_stage(sb, 0, 0, bm, bn, tid);
    CP_COMMIT();
    load_stage(sb, 1, 1, bm, bn, tid);
    CP_COMMIT();

    for (int kt = 0; kt < KITERS; kt++) {
        CP_WAIT1();                    // stage kt resident
        __syncthreads();               // all warps past stage kt-1 (slot kt+2 reusable)

        if (kt + 2 < KITERS)
            load_stage(sb, (kt + 2) % STAGES, kt + 2, bm, bn, tid);
        CP_COMMIT();

        uint32_t abase = sb + (kt % STAGES) * STAGE_B;
        uint32_t bbase = abase + A_STAGE_B;

        #pragma unroll
        for (int ks = 0; ks < 4; ks++) {
            int ko = ks * 16;

            uint32_t af[4][4];
            #pragma unroll
            for (int mi = 0; mi < 4; mi++) {
                int arow = wm * 64 + mi * 16 + r8 + (q & 1) * 8;
                int acol = ko + (q >> 1) * 8;
                ldmatrix_x4(af[mi], abase + (uint32_t)(arow * LDA + acol) * 2);
            }

            uint32_t bfr[4][2];
            #pragma unroll
            for (int ni = 0; ni < 2; ni++) {
                int brow = ko + (q & 1) * 8 + r8;
                int bcol = wn * 32 + ni * 16 + (q >> 1) * 8;
                uint32_t t4[4];
                ldmatrix_x4_trans(t4, bbase + (uint32_t)(brow * LDB + bcol) * 2);
                bfr[ni * 2 + 0][0] = t4[0]; bfr[ni * 2 + 0][1] = t4[1];
                bfr[ni * 2 + 1][0] = t4[2]; bfr[ni * 2 + 1][1] = t4[3];
            }

            #pragma unroll
            for (int mi = 0; mi < 4; mi++)
                #pragma unroll
                for (int nb = 0; nb < 4; nb++)
                    mma_16816(acc[mi][nb], af[mi], bfr[nb]);
        }
    }

    // epilogue: out = 3*tanh((acc + bias)*scale/3)
    float sc3 = scale[0] * (1.0f / 3.0f);
    int rr = lane >> 2;
    int cq = (lane & 3) * 2;

    #pragma unroll
    for (int nb = 0; nb < 4; nb++) {
        int col = bn * BN + wn * 32 + nb * 8 + cq;
        float2 bv = *(const float2*)(bias + col);
        #pragma unroll
        for (int mi = 0; mi < 4; mi++) {
            int row = bm * BM + wm * 64 + mi * 16 + rr;
            float2 o0, o1;
            o0.x = fast_tanh3(acc[mi][nb][0] + bv.x, sc3);
            o0.y = fast_tanh3(acc[mi][nb][1] + bv.y, sc3);
            o1.x = fast_tanh3(acc[mi][nb][2] + bv.x, sc3);
            o1.y = fast_tanh3(acc[mi][nb][3] + bv.y, sc3);
            *(float2*)(out + (size_t)row * D_MODEL + col)       = o0;
            *(float2*)(out + (size_t)(row + 8) * D_MODEL + col) = o1;
        }
    }
}

// ---------------------------------------------------------------- launch
extern "C" void kernel_launch(void* const* d_in, const int* in_sizes, int n_in,
                              void* d_out, int out_size) {
    const float* z     = (const float*)d_in[0];
    const float* gamma = (const float*)d_in[1];
    const float* beta  = (const float*)d_in[2];
    const float* W     = (const float*)d_in[3];
    const float* b     = (const float*)d_in[4];
    const float* scale = (const float*)d_in[5];
    float* out = (float*)d_out;
    (void)in_sizes; (void)n_in; (void)out_size;

    cudaFuncSetAttribute(gemm_kernel, cudaFuncAttributeMaxDynamicSharedMemorySize, SMEM_TOTAL);

    wconv_kernel<<<4096, 256>>>(W);
    ln_kernel<<<M_ROWS, 256>>>(z, gamma, beta);
    dim3 grid(D_MODEL / BN, M_ROWS / BM);   // (32, 64)
    gemm_kernel<<<grid, 512, SMEM_TOTAL>>>(b, scale, out);
}

// round 6
// speedup vs baseline: 1.3260x; 1.1531x over previous
#include <cuda_runtime.h>
#include <cuda_fp16.h>
#include <cstdint>

// ---------------------------------------------------------------- constants
#define D_Z     1024
#define D_MODEL 4096
#define M_ROWS  16384
#define EPS     1e-5f

#define BM 128
#define BN 128
#define BK 64
#define KITERS (D_Z / BK)      // 16
#define STAGES 3

#define LDA 72                  // 64 + 8 pad (fp16): conflict-free ldmatrix
#define LDB 136                 // 128 + 8 pad
#define A_STAGE_B (BM * LDA * 2)          // 18432 B
#define B_STAGE_B (BK * LDB * 2)          // 17408 B
#define STAGE_B   (A_STAGE_B + B_STAGE_B) // 35840 B
#define SMEM_TOTAL (STAGES * STAGE_B)     // 107520 B -> 2 CTAs/SM

// scratch (allocation-free rule: device globals)
__device__ __half g_zn[(size_t)M_ROWS * D_Z];     // LN output fp16 [M,K]
__device__ __half g_wb[(size_t)D_Z * D_MODEL];    // W fp16 [K,N]

// ---------------------------------------------------------------- K1: merged prep
// blocks [0, M_ROWS): LayerNorm row -> fp16 ; blocks [M_ROWS, M_ROWS+4096): W convert
__global__ __launch_bounds__(256) void prep_kernel(const float* __restrict__ z,
                                                   const float* __restrict__ gamma,
                                                   const float* __restrict__ beta,
                                                   const float* __restrict__ W) {
    int blk = blockIdx.x;
    int t   = threadIdx.x;

    if (blk >= M_ROWS) {
        // ---- W fp32 -> fp16 (one float4 per thread)
        size_t i = (size_t)(blk - M_ROWS) * 256 + t;
        float4 v = ((const float4*)W)[i];
        __half2* dst = (__half2*)g_wb;
        dst[i * 2 + 0] = __floats2half2_rn(v.x, v.y);
        dst[i * 2 + 1] = __floats2half2_rn(v.z, v.w);
        return;
    }

    // ---- LayerNorm
    int row = blk, lane = t & 31, wid = t >> 5;
    const float4* zp = (const float4*)(z + (size_t)row * D_Z);
    float4 v = zp[t];

    float s  = v.x + v.y + v.z + v.w;
    float ss = v.x * v.x + v.y * v.y + v.z * v.z + v.w * v.w;
    #pragma unroll
    for (int o = 16; o > 0; o >>= 1) {
        s  += __shfl_xor_sync(0xffffffffu, s, o);
        ss += __shfl_xor_sync(0xffffffffu, ss, o);
    }
    __shared__ float sbuf[8], ssbuf[8], smu, srstd;
    if (lane == 0) { sbuf[wid] = s; ssbuf[wid] = ss; }
    __syncthreads();
    if (t == 0) {
        float S = 0.f, SS = 0.f;
        #pragma unroll
        for (int i = 0; i < 8; i++) { S += sbuf[i]; SS += ssbuf[i]; }
        float mu  = S * (1.0f / D_Z);
        float var = SS * (1.0f / D_Z) - mu * mu;
        smu = mu; srstd = rsqrtf(var + EPS);
    }
    __syncthreads();
    float mu = smu, rstd = srstd;

    float4 g = ((const float4*)gamma)[t];
    float4 b = ((const float4*)beta)[t];
    float o0 = (v.x - mu) * rstd * g.x + b.x;
    float o1 = (v.y - mu) * rstd * g.y + b.y;
    float o2 = (v.z - mu) * rstd * g.z + b.z;
    float o3 = (v.w - mu) * rstd * g.w + b.w;

    __half2* dst = (__half2*)(g_zn + (size_t)row * D_Z);
    dst[t * 2 + 0] = __floats2half2_rn(o0, o1);
    dst[t * 2 + 1] = __floats2half2_rn(o2, o3);
}

// ---------------------------------------------------------------- PTX wrappers
__device__ __forceinline__ void ldmatrix_x4(uint32_t r[4], uint32_t addr) {
    asm volatile("ldmatrix.sync.aligned.m8n8.x4.shared.b16 {%0,%1,%2,%3}, [%4];\n"
                 : "=r"(r[0]), "=r"(r[1]), "=r"(r[2]), "=r"(r[3]) : "r"(addr));
}
__device__ __forceinline__ void ldmatrix_x4_trans(uint32_t r[4], uint32_t addr) {
    asm volatile("ldmatrix.sync.aligned.m8n8.x4.trans.shared.b16 {%0,%1,%2,%3}, [%4];\n"
                 : "=r"(r[0]), "=r"(r[1]), "=r"(r[2]), "=r"(r[3]) : "r"(addr));
}
__device__ __forceinline__ void mma_16816(float c[4], const uint32_t a[4], const uint32_t b[2]) {
    asm volatile("mma.sync.aligned.m16n8k16.row.col.f32.f16.f16.f32 "
                 "{%0,%1,%2,%3}, {%4,%5,%6,%7}, {%8,%9}, {%0,%1,%2,%3};\n"
                 : "+f"(c[0]), "+f"(c[1]), "+f"(c[2]), "+f"(c[3])
                 : "r"(a[0]), "r"(a[1]), "r"(a[2]), "r"(a[3]), "r"(b[0]), "r"(b[1]));
}
__device__ __forceinline__ void cp_async16(uint32_t dst, const void* src) {
    asm volatile("cp.async.cg.shared.global [%0], [%1], 16;\n" :: "r"(dst), "l"(src) : "memory");
}
#define CP_COMMIT() asm volatile("cp.async.commit_group;" ::: "memory")
#define CP_WAIT1()  asm volatile("cp.async.wait_group 1;" ::: "memory")

// fast tanh: tanh(t) = 1 - 2/(exp(2t)+1), rel err ~1e-6
__device__ __forceinline__ float fast_tanh3(float x, float sc3) {
    float t = x * sc3;
    float e;
    asm("ex2.approx.f32 %0, %1;" : "=f"(e) : "f"(t * 2.885390082f));
    float r;
    asm("rcp.approx.f32 %0, %1;" : "=f"(r) : "f"(e + 1.0f));
    return 3.0f * (1.0f - 2.0f * r);
}

// ---------------------------------------------------------------- K2: pipelined HMMA GEMM
__device__ __forceinline__ void load_stage(uint32_t sb, int slot, int kt, int bm, int bn, int tid) {
    uint32_t abase = sb + slot * STAGE_B;
    uint32_t bbase = abase + A_STAGE_B;
    // A: 128 rows x 64 f16 = 1024 x 16B chunks, 4/thread
    const char* Ag = (const char*)(g_zn + (size_t)(bm * BM) * D_Z + kt * BK);
    #pragma unroll
    for (int i = 0; i < 4; i++) {
        int chunk = tid + i * 256;
        int row = chunk >> 3, c = chunk & 7;
        cp_async16(abase + (uint32_t)(row * LDA + c * 8) * 2,
                   Ag + (size_t)row * (D_Z * 2) + c * 16);
    }
    // B: 64 rows x 128 f16 = 1024 x 16B chunks, 4/thread
    const char* Bg = (const char*)(g_wb + (size_t)(kt * BK) * D_MODEL + bn * BN);
    #pragma unroll
    for (int i = 0; i < 4; i++) {
        int chunk = tid + i * 256;
        int row = chunk >> 4, c = chunk & 15;
        cp_async16(bbase + (uint32_t)(row * LDB + c * 8) * 2,
                   Bg + (size_t)row * (D_MODEL * 2) + c * 16);
    }
}

__global__ __launch_bounds__(256, 2) void gemm_kernel(const float* __restrict__ bias,
                                                      const float* __restrict__ scale,
                                                      float* __restrict__ out) {
    extern __shared__ __align__(16) char smem[];
    uint32_t sb;
    asm("{ .reg .u64 t; cvta.to.shared.u64 t, %1; cvt.u32.u64 %0, t; }" : "=r"(sb) : "l"(smem));

    int tid  = threadIdx.x;
    int wid  = tid >> 5;
    int lane = tid & 31;
    int wm   = wid >> 2;        // 0..1 (64 rows)
    int wn   = wid & 3;         // 0..3 (32 cols)
    int bm   = blockIdx.y;
    int bn   = blockIdx.x;

    float acc[4][4][4];
    #pragma unroll
    for (int i = 0; i < 4; i++)
        #pragma unroll
        for (int j = 0; j < 4; j++)
            #pragma unroll
            for (int k = 0; k < 4; k++) acc[i][j][k] = 0.f;

    int r8 = lane & 7;
    int q  = lane >> 3;

    load_stage(sb, 0, 0, bm, bn, tid);
    CP_COMMIT();
    load_stage(sb, 1, 1, bm, bn, tid);
    CP_COMMIT();

    for (int kt = 0; kt < KITERS; kt++) {
        CP_WAIT1();
        __syncthreads();

        if (kt + 2 < KITERS)
            load_stage(sb, (kt + 2) % STAGES, kt + 2, bm, bn, tid);
        CP_COMMIT();

        uint32_t abase = sb + (kt % STAGES) * STAGE_B;
        uint32_t bbase = abase + A_STAGE_B;

        #pragma unroll
        for (int ks = 0; ks < 4; ks++) {
            int ko = ks * 16;

            uint32_t af[4][4];
            #pragma unroll
            for (int mi = 0; mi < 4; mi++) {
                int arow = wm * 64 + mi * 16 + r8 + (q & 1) * 8;
                int acol = ko + (q >> 1) * 8;
                ldmatrix_x4(af[mi], abase + (uint32_t)(arow * LDA + acol) * 2);
            }

            uint32_t bfr[4][2];
            #pragma unroll
            for (int ni = 0; ni < 2; ni++) {
                int brow = ko + (q & 1) * 8 + r8;
                int bcol = wn * 32 + ni * 16 + (q >> 1) * 8;
                uint32_t t4[4];
                ldmatrix_x4_trans(t4, bbase + (uint32_t)(brow * LDB + bcol) * 2);
                bfr[ni * 2 + 0][0] = t4[0]; bfr[ni * 2 + 0][1] = t4[1];
                bfr[ni * 2 + 1][0] = t4[2]; bfr[ni * 2 + 1][1] = t4[3];
            }

            #pragma unroll
            for (int mi = 0; mi < 4; mi++)
                #pragma unroll
                for (int nb = 0; nb < 4; nb++)
                    mma_16816(acc[mi][nb], af[mi], bfr[nb]);
        }
    }

    // epilogue: out = 3*tanh((acc + bias)*scale/3)
    float sc3 = scale[0] * (1.0f / 3.0f);
    int rr = lane >> 2;
    int cq = (lane & 3) * 2;

    #pragma unroll
    for (int nb = 0; nb < 4; nb++) {
        int col = bn * BN + wn * 32 + nb * 8 + cq;
        float2 bv = *(const float2*)(bias + col);
        #pragma unroll
        for (int mi = 0; mi < 4; mi++) {
            int row = bm * BM + wm * 64 + mi * 16 + rr;
            float2 o0, o1;
            o0.x = fast_tanh3(acc[mi][nb][0] + bv.x, sc3);
            o0.y = fast_tanh3(acc[mi][nb][1] + bv.y, sc3);
            o1.x = fast_tanh3(acc[mi][nb][2] + bv.x, sc3);
            o1.y = fast_tanh3(acc[mi][nb][3] + bv.y, sc3);
            *(float2*)(out + (size_t)row * D_MODEL + col)       = o0;
            *(float2*)(out + (size_t)(row + 8) * D_MODEL + col) = o1;
        }
    }
}

// ---------------------------------------------------------------- launch
extern "C" void kernel_launch(void* const* d_in, const int* in_sizes, int n_in,
                              void* d_out, int out_size) {
    const float* z     = (const float*)d_in[0];
    const float* gamma = (const float*)d_in[1];
    const float* beta  = (const float*)d_in[2];
    const float* W     = (const float*)d_in[3];
    const float* b     = (const float*)d_in[4];
    const float* scale = (const float*)d_in[5];
    float* out = (float*)d_out;
    (void)in_sizes; (void)n_in; (void)out_size;

    cudaFuncSetAttribute(gemm_kernel, cudaFuncAttributeMaxDynamicSharedMemorySize, SMEM_TOTAL);

    // merged LN + W-convert (concurrent, both memory-bound)
    prep_kernel<<<M_ROWS + (D_Z * D_MODEL / 4) / 256, 256>>>(z, gamma, beta, W);
    dim3 grid(D_MODEL / BN, M_ROWS / BM);   // (32, 128) = 4096 CTAs, 2/SM
    gemm_kernel<<<grid, 256, SMEM_TOTAL>>>(b, scale, out);
}

// round 7
// speedup vs baseline: 1.3427x; 1.0126x over previous
#include <cuda_runtime.h>
#include <cuda_fp16.h>
#include <cstdint>

// ---------------------------------------------------------------- constants
#define D_Z     1024
#define D_MODEL 4096
#define M_ROWS  16384
#define EPS     1e-5f

#define BM 128
#define BN 128
#define BK 64
#define KITERS (D_Z / BK)      // 16
#define STAGES 3

#define LDA 72                  // 64 + 8 pad (fp16): conflict-free ldmatrix
#define LDB 136                 // 128 + 8 pad
#define A_STAGE_B (BM * LDA * 2)          // 18432 B
#define B_STAGE_B (BK * LDB * 2)          // 17408 B
#define STAGE_B   (A_STAGE_B + B_STAGE_B) // 35840 B
#define SMEM_TOTAL (STAGES * STAGE_B)     // 107520 B -> 2 CTAs/SM

#define WCONV_BLOCKS 1024       // 1M float4 / (256 thr * 4)

// scratch (allocation-free rule: device globals)
__device__ __half g_zn[(size_t)M_ROWS * D_Z];     // LN output fp16 [M,K]
__device__ __half g_wb[(size_t)D_Z * D_MODEL];    // W fp16 [K,N]

// ---------------------------------------------------------------- K1: merged prep
__global__ __launch_bounds__(256) void prep_kernel(const float* __restrict__ z,
                                                   const float* __restrict__ gamma,
                                                   const float* __restrict__ beta,
                                                   const float* __restrict__ W) {
    int blk = blockIdx.x;
    int t   = threadIdx.x;

    if (blk >= M_ROWS) {
        // ---- W fp32 -> fp16, 4 float4 per thread
        size_t base = (size_t)(blk - M_ROWS) * 1024 + t;
        __half2* dst = (__half2*)g_wb;
        #pragma unroll
        for (int u = 0; u < 4; u++) {
            size_t i = base + (size_t)u * 256;
            float4 v = ((const float4*)W)[i];
            dst[i * 2 + 0] = __floats2half2_rn(v.x, v.y);
            dst[i * 2 + 1] = __floats2half2_rn(v.z, v.w);
        }
        return;
    }

    // ---- LayerNorm
    int row = blk, lane = t & 31, wid = t >> 5;
    const float4* zp = (const float4*)(z + (size_t)row * D_Z);
    float4 v = zp[t];

    float s  = v.x + v.y + v.z + v.w;
    float ss = v.x * v.x + v.y * v.y + v.z * v.z + v.w * v.w;
    #pragma unroll
    for (int o = 16; o > 0; o >>= 1) {
        s  += __shfl_xor_sync(0xffffffffu, s, o);
        ss += __shfl_xor_sync(0xffffffffu, ss, o);
    }
    __shared__ float sbuf[8], ssbuf[8], smu, srstd;
    if (lane == 0) { sbuf[wid] = s; ssbuf[wid] = ss; }
    __syncthreads();
    if (t == 0) {
        float S = 0.f, SS = 0.f;
        #pragma unroll
        for (int i = 0; i < 8; i++) { S += sbuf[i]; SS += ssbuf[i]; }
        float mu  = S * (1.0f / D_Z);
        float var = SS * (1.0f / D_Z) - mu * mu;
        smu = mu; srstd = rsqrtf(var + EPS);
    }
    __syncthreads();
    float mu = smu, rstd = srstd;

    float4 g = ((const float4*)gamma)[t];
    float4 b = ((const float4*)beta)[t];
    float o0 = (v.x - mu) * rstd * g.x + b.x;
    float o1 = (v.y - mu) * rstd * g.y + b.y;
    float o2 = (v.z - mu) * rstd * g.z + b.z;
    float o3 = (v.w - mu) * rstd * g.w + b.w;

    __half2* dst = (__half2*)(g_zn + (size_t)row * D_Z);
    dst[t * 2 + 0] = __floats2half2_rn(o0, o1);
    dst[t * 2 + 1] = __floats2half2_rn(o2, o3);
}

// ---------------------------------------------------------------- PTX wrappers
__device__ __forceinline__ void ldmatrix_x4(uint32_t r[4], uint32_t addr) {
    asm volatile("ldmatrix.sync.aligned.m8n8.x4.shared.b16 {%0,%1,%2,%3}, [%4];\n"
                 : "=r"(r[0]), "=r"(r[1]), "=r"(r[2]), "=r"(r[3]) : "r"(addr));
}
__device__ __forceinline__ void ldmatrix_x4_trans(uint32_t r[4], uint32_t addr) {
    asm volatile("ldmatrix.sync.aligned.m8n8.x4.trans.shared.b16 {%0,%1,%2,%3}, [%4];\n"
                 : "=r"(r[0]), "=r"(r[1]), "=r"(r[2]), "=r"(r[3]) : "r"(addr));
}
__device__ __forceinline__ void mma_16816(float c[4], const uint32_t a[4], const uint32_t b[2]) {
    asm volatile("mma.sync.aligned.m16n8k16.row.col.f32.f16.f16.f32 "
                 "{%0,%1,%2,%3}, {%4,%5,%6,%7}, {%8,%9}, {%0,%1,%2,%3};\n"
                 : "+f"(c[0]), "+f"(c[1]), "+f"(c[2]), "+f"(c[3])
                 : "r"(a[0]), "r"(a[1]), "r"(a[2]), "r"(a[3]), "r"(b[0]), "r"(b[1]));
}
__device__ __forceinline__ void cp_async16(uint32_t dst, const void* src) {
    asm volatile("cp.async.cg.shared.global [%0], [%1], 16;\n" :: "r"(dst), "l"(src) : "memory");
}
#define CP_COMMIT() asm volatile("cp.async.commit_group;" ::: "memory")
#define CP_WAIT1()  asm volatile("cp.async.wait_group 1;" ::: "memory")

// fast tanh: tanh(t) = 1 - 2/(exp(2t)+1), rel err ~1e-6
__device__ __forceinline__ float fast_tanh3(float x, float sc3) {
    float t = x * sc3;
    float e;
    asm("ex2.approx.f32 %0, %1;" : "=f"(e) : "f"(t * 2.885390082f));
    float r;
    asm("rcp.approx.f32 %0, %1;" : "=f"(r) : "f"(e + 1.0f));
    return 3.0f * (1.0f - 2.0f * r);
}

// ---------------------------------------------------------------- K2: pipelined HMMA GEMM
__device__ __forceinline__ void load_stage(uint32_t sb, int slot, int kt, int bm, int bn, int tid) {
    uint32_t abase = sb + slot * STAGE_B;
    uint32_t bbase = abase + A_STAGE_B;
    const char* Ag = (const char*)(g_zn + (size_t)(bm * BM) * D_Z + kt * BK);
    #pragma unroll
    for (int i = 0; i < 4; i++) {
        int chunk = tid + i * 256;
        int row = chunk >> 3, c = chunk & 7;
        cp_async16(abase + (uint32_t)(row * LDA + c * 8) * 2,
                   Ag + (size_t)row * (D_Z * 2) + c * 16);
    }
    const char* Bg = (const char*)(g_wb + (size_t)(kt * BK) * D_MODEL + bn * BN);
    #pragma unroll
    for (int i = 0; i < 4; i++) {
        int chunk = tid + i * 256;
        int row = chunk >> 4, c = chunk & 15;
        cp_async16(bbase + (uint32_t)(row * LDB + c * 8) * 2,
                   Bg + (size_t)row * (D_MODEL * 2) + c * 16);
    }
}

__global__ __launch_bounds__(256, 2) void gemm_kernel(const float* __restrict__ bias,
                                                      const float* __restrict__ scale,
                                                      float* __restrict__ out) {
    extern __shared__ __align__(16) char smem[];
    uint32_t sb;
    asm("{ .reg .u64 t; cvta.to.shared.u64 t, %1; cvt.u32.u64 %0, t; }" : "=r"(sb) : "l"(smem));

    int tid  = threadIdx.x;
    int wid  = tid >> 5;
    int lane = tid & 31;
    int wm   = wid >> 2;        // 0..1 (64 rows)
    int wn   = wid & 3;         // 0..3 (32 cols)
    int bm   = blockIdx.y;
    int bn   = blockIdx.x;

    float acc[4][4][4];
    #pragma unroll
    for (int i = 0; i < 4; i++)
        #pragma unroll
        for (int j = 0; j < 4; j++)
            #pragma unroll
            for (int k = 0; k < 4; k++) acc[i][j][k] = 0.f;

    int r8 = lane & 7;
    int q  = lane >> 3;

    // precomputed per-thread ldmatrix offsets (bytes, within stage)
    uint32_t aoff[4], boff[2];
    #pragma unroll
    for (int mi = 0; mi < 4; mi++)
        aoff[mi] = (uint32_t)((wm * 64 + mi * 16 + r8 + (q & 1) * 8) * LDA + (q >> 1) * 8) * 2;
    #pragma unroll
    for (int ni = 0; ni < 2; ni++)
        boff[ni] = (uint32_t)(((q & 1) * 8 + r8) * LDB + wn * 32 + ni * 16 + (q >> 1) * 8) * 2;

    load_stage(sb, 0, 0, bm, bn, tid);
    CP_COMMIT();
    load_stage(sb, 1, 1, bm, bn, tid);
    CP_COMMIT();

    uint32_t af0[2][4], af1[2][4];   // A mi{0,1} / mi{2,3}
    uint32_t bfr[2][4][2];           // B double buffer across ks

    for (int kt = 0; kt < KITERS; kt++) {
        CP_WAIT1();
        __syncthreads();

        uint32_t abase = sb + (kt % STAGES) * STAGE_B;
        uint32_t bbase = abase + A_STAGE_B;

        // iteration prologue: fragments for ks=0 before the cp.async burst
        {
            uint32_t t4[4];
            ldmatrix_x4_trans(t4, bbase + boff[0]);
            bfr[0][0][0] = t4[0]; bfr[0][0][1] = t4[1];
            bfr[0][1][0] = t4[2]; bfr[0][1][1] = t4[3];
            ldmatrix_x4_trans(t4, bbase + boff[1]);
            bfr[0][2][0] = t4[0]; bfr[0][2][1] = t4[1];
            bfr[0][3][0] = t4[2]; bfr[0][3][1] = t4[3];
            ldmatrix_x4(af0[0], abase + aoff[0]);
            ldmatrix_x4(af0[1], abase + aoff[1]);
        }

        if (kt + 2 < KITERS)
            load_stage(sb, (kt + 2) % STAGES, kt + 2, bm, bn, tid);
        CP_COMMIT();

        #pragma unroll
        for (int ks = 0; ks < 4; ks++) {
            int cur = ks & 1;
            uint32_t ko2 = (uint32_t)(ks * 16) * 2;              // A col byte offset
            uint32_t kb  = (uint32_t)(ks * 16) * (LDB * 2);      // B row byte offset

            // A half1 of current ks
            ldmatrix_x4(af1[0], abase + aoff[2] + ko2);
            ldmatrix_x4(af1[1], abase + aoff[3] + ko2);

            // B for ks+1 (alternate buffer)
            if (ks < 3) {
                uint32_t kb1 = kb + (uint32_t)(LDB * 2) * 16;
                uint32_t t4[4];
                ldmatrix_x4_trans(t4, bbase + boff[0] + kb1);
                bfr[cur ^ 1][0][0] = t4[0]; bfr[cur ^ 1][0][1] = t4[1];
                bfr[cur ^ 1][1][0] = t4[2]; bfr[cur ^ 1][1][1] = t4[3];
                ldmatrix_x4_trans(t4, bbase + boff[1] + kb1);
                bfr[cur ^ 1][2][0] = t4[0]; bfr[cur ^ 1][2][1] = t4[1];
                bfr[cur ^ 1][3][0] = t4[2]; bfr[cur ^ 1][3][1] = t4[3];
            }

            // MMAs on half0 (mi 0,1)
            #pragma unroll
            for (int mi = 0; mi < 2; mi++)
                #pragma unroll
                for (int nb = 0; nb < 4; nb++)
                    mma_16816(acc[mi][nb], af0[mi], bfr[cur][nb]);

            // A half0 of next ks (overwrites af0 while half1 MMAs run)
            if (ks < 3) {
                ldmatrix_x4(af0[0], abase + aoff[0] + ko2 + 32);
                ldmatrix_x4(af0[1], abase + aoff[1] + ko2 + 32);
            }

            // MMAs on half1 (mi 2,3)
            #pragma unroll
            for (int mi = 0; mi < 2; mi++)
                #pragma unroll
                for (int nb = 0; nb < 4; nb++)
                    mma_16816(acc[mi + 2][nb], af1[mi], bfr[cur][nb]);
        }
    }

    // epilogue: out = 3*tanh((acc + bias)*scale/3)
    float sc3 = scale[0] * (1.0f / 3.0f);
    int rr = lane >> 2;
    int cq = (lane & 3) * 2;

    #pragma unroll
    for (int nb = 0; nb < 4; nb++) {
        int col = bn * BN + wn * 32 + nb * 8 + cq;
        float2 bv = *(const float2*)(bias + col);
        #pragma unroll
        for (int mi = 0; mi < 4; mi++) {
            int row = bm * BM + wm * 64 + mi * 16 + rr;
            float2 o0, o1;
            o0.x = fast_tanh3(acc[mi][nb][0] + bv.x, sc3);
            o0.y = fast_tanh3(acc[mi][nb][1] + bv.y, sc3);
            o1.x = fast_tanh3(acc[mi][nb][2] + bv.x, sc3);
            o1.y = fast_tanh3(acc[mi][nb][3] + bv.y, sc3);
            *(float2*)(out + (size_t)row * D_MODEL + col)       = o0;
            *(float2*)(out + (size_t)(row + 8) * D_MODEL + col) = o1;
        }
    }
}

// ---------------------------------------------------------------- launch
extern "C" void kernel_launch(void* const* d_in, const int* in_sizes, int n_in,
                              void* d_out, int out_size) {
    const float* z     = (const float*)d_in[0];
    const float* gamma = (const float*)d_in[1];
    const float* beta  = (const float*)d_in[2];
    const float* W     = (const float*)d_in[3];
    const float* b     = (const float*)d_in[4];
    const float* scale = (const float*)d_in[5];
    float* out = (float*)d_out;
    (void)in_sizes; (void)n_in; (void)out_size;

    cudaFuncSetAttribute(gemm_kernel, cudaFuncAttributeMaxDynamicSharedMemorySize, SMEM_TOTAL);

    prep_kernel<<<M_ROWS + WCONV_BLOCKS, 256>>>(z, gamma, beta, W);
    dim3 grid(D_MODEL / BN, M_ROWS / BM);   // (32, 128) = 4096 CTAs, 2/SM
    gemm_kernel<<<grid, 256, SMEM_TOTAL>>>(b, scale, out);
}

// round 8
// speedup vs baseline: 1.3505x; 1.0058x over previous
#include <cuda_runtime.h>
#include <cuda_fp16.h>
#include <cstdint>

// ---------------------------------------------------------------- constants
#define D_Z     1024
#define D_MODEL 4096
#define M_ROWS  16384
#define EPS     1e-5f

#define BM 128
#define BN 128
#define BK 64
#define KITERS (D_Z / BK)      // 16
#define STAGES 3

#define LDA 72                  // 64 + 8 pad (fp16): conflict-free ldmatrix
#define LDB 136                 // 128 + 8 pad
#define A_STAGE_B (BM * LDA * 2)          // 18432 B
#define B_STAGE_B (BK * LDB * 2)          // 17408 B
#define STAGE_B   (A_STAGE_B + B_STAGE_B) // 35840 B
#define SMEM_TOTAL (STAGES * STAGE_B)     // 107520 B -> 2 CTAs/SM

#define WCONV_BLOCKS 1024

// scratch (allocation-free rule: device globals)
__device__ __half g_zn[(size_t)M_ROWS * D_Z];     // LN output fp16 [M,K]
__device__ __half g_wb[(size_t)D_Z * D_MODEL];    // W fp16 [K,N]

// ---------------------------------------------------------------- K1: merged prep
__global__ __launch_bounds__(256) void prep_kernel(const float* __restrict__ z,
                                                   const float* __restrict__ gamma,
                                                   const float* __restrict__ beta,
                                                   const float* __restrict__ W) {
    int blk = blockIdx.x;
    int t   = threadIdx.x;

    if (blk >= M_ROWS) {
        size_t base = (size_t)(blk - M_ROWS) * 1024 + t;
        __half2* dst = (__half2*)g_wb;
        #pragma unroll
        for (int u = 0; u < 4; u++) {
            size_t i = base + (size_t)u * 256;
            float4 v = ((const float4*)W)[i];
            dst[i * 2 + 0] = __floats2half2_rn(v.x, v.y);
            dst[i * 2 + 1] = __floats2half2_rn(v.z, v.w);
        }
        return;
    }

    int row = blk, lane = t & 31, wid = t >> 5;
    const float4* zp = (const float4*)(z + (size_t)row * D_Z);
    float4 v = zp[t];

    float s  = v.x + v.y + v.z + v.w;
    float ss = v.x * v.x + v.y * v.y + v.z * v.z + v.w * v.w;
    #pragma unroll
    for (int o = 16; o > 0; o >>= 1) {
        s  += __shfl_xor_sync(0xffffffffu, s, o);
        ss += __shfl_xor_sync(0xffffffffu, ss, o);
    }
    __shared__ float sbuf[8], ssbuf[8], smu, srstd;
    if (lane == 0) { sbuf[wid] = s; ssbuf[wid] = ss; }
    __syncthreads();
    if (t == 0) {
        float S = 0.f, SS = 0.f;
        #pragma unroll
        for (int i = 0; i < 8; i++) { S += sbuf[i]; SS += ssbuf[i]; }
        float mu  = S * (1.0f / D_Z);
        float var = SS * (1.0f / D_Z) - mu * mu;
        smu = mu; srstd = rsqrtf(var + EPS);
    }
    __syncthreads();
    float mu = smu, rstd = srstd;

    float4 g = ((const float4*)gamma)[t];
    float4 b = ((const float4*)beta)[t];
    float o0 = (v.x - mu) * rstd * g.x + b.x;
    float o1 = (v.y - mu) * rstd * g.y + b.y;
    float o2 = (v.z - mu) * rstd * g.z + b.z;
    float o3 = (v.w - mu) * rstd * g.w + b.w;

    __half2* dst = (__half2*)(g_zn + (size_t)row * D_Z);
    dst[t * 2 + 0] = __floats2half2_rn(o0, o1);
    dst[t * 2 + 1] = __floats2half2_rn(o2, o3);
}

// ---------------------------------------------------------------- PTX wrappers
__device__ __forceinline__ void ldmatrix_x4(uint32_t r[4], uint32_t addr) {
    asm volatile("ldmatrix.sync.aligned.m8n8.x4.shared.b16 {%0,%1,%2,%3}, [%4];\n"
                 : "=r"(r[0]), "=r"(r[1]), "=r"(r[2]), "=r"(r[3]) : "r"(addr));
}
// direct-write trans variant: {t0,t1}->tile lo, {t2,t3}->tile hi
__device__ __forceinline__ void ldmatrix_b(uint32_t& b00, uint32_t& b01,
                                           uint32_t& b10, uint32_t& b11, uint32_t addr) {
    asm volatile("ldmatrix.sync.aligned.m8n8.x4.trans.shared.b16 {%0,%1,%2,%3}, [%4];\n"
                 : "=r"(b00), "=r"(b01), "=r"(b10), "=r"(b11) : "r"(addr));
}
__device__ __forceinline__ void mma_16816(float c[4], const uint32_t a[4],
                                          uint32_t b0, uint32_t b1) {
    asm volatile("mma.sync.aligned.m16n8k16.row.col.f32.f16.f16.f32 "
                 "{%0,%1,%2,%3}, {%4,%5,%6,%7}, {%8,%9}, {%0,%1,%2,%3};\n"
                 : "+f"(c[0]), "+f"(c[1]), "+f"(c[2]), "+f"(c[3])
                 : "r"(a[0]), "r"(a[1]), "r"(a[2]), "r"(a[3]), "r"(b0), "r"(b1));
}
__device__ __forceinline__ void cp_async16(uint32_t dst, const void* src) {
    asm volatile("cp.async.cg.shared.global [%0], [%1], 16;\n" :: "r"(dst), "l"(src) : "memory");
}
#define CP_COMMIT() asm volatile("cp.async.commit_group;" ::: "memory")
#define CP_WAIT1()  asm volatile("cp.async.wait_group 1;" ::: "memory")

// fast tanh: tanh(t) = 1 - 2/(exp(2t)+1), rel err ~1e-6
__device__ __forceinline__ float fast_tanh3(float x, float sc3) {
    float t = x * sc3;
    float e;
    asm("ex2.approx.f32 %0, %1;" : "=f"(e) : "f"(t * 2.885390082f));
    float r;
    asm("rcp.approx.f32 %0, %1;" : "=f"(r) : "f"(e + 1.0f));
    return 3.0f * (1.0f - 2.0f * r);
}

// ---------------------------------------------------------------- K2: pipelined HMMA GEMM
__global__ __launch_bounds__(256, 2) void gemm_kernel(const float* __restrict__ bias,
                                                      const float* __restrict__ scale,
                                                      float* __restrict__ out) {
    extern __shared__ __align__(16) char smem[];
    uint32_t sb;
    asm("{ .reg .u64 t; cvta.to.shared.u64 t, %1; cvt.u32.u64 %0, t; }" : "=r"(sb) : "l"(smem));

    int tid  = threadIdx.x;
    int wid  = tid >> 5;
    int lane = tid & 31;
    int wm   = wid >> 2;        // 0..1 (64 rows)
    int wn   = wid & 3;         // 0..3 (32 cols)
    int bm   = blockIdx.y;
    int bn   = blockIdx.x;

    float acc[4][4][4];
    #pragma unroll
    for (int i = 0; i < 4; i++)
        #pragma unroll
        for (int j = 0; j < 4; j++)
            #pragma unroll
            for (int k = 0; k < 4; k++) acc[i][j][k] = 0.f;

    int r8 = lane & 7;
    int q  = lane >> 3;

    // ---- per-thread constant offsets -----------------------------------
    // ldmatrix offsets (bytes within a stage)
    uint32_t aoff[4], boff[2];
    #pragma unroll
    for (int mi = 0; mi < 4; mi++)
        aoff[mi] = (uint32_t)((wm * 64 + mi * 16 + r8 + (q & 1) * 8) * LDA + (q >> 1) * 8) * 2;
    #pragma unroll
    for (int ni = 0; ni < 2; ni++)
        boff[ni] = (uint32_t)(((q & 1) * 8 + r8) * LDB + wn * 32 + ni * 16 + (q >> 1) * 8) * 2 + A_STAGE_B;

    // cp.async offsets: A 4 chunks, B 4 chunks per thread
    uint32_t as_off[4], bs_off[4];
    uint32_t ag_off[4], bg_off[4];      // gmem byte offsets (fit in 32b: <32MB per tile walk handled by ptr)
    #pragma unroll
    for (int i = 0; i < 4; i++) {
        int chunk = tid + i * 256;
        int arow = chunk >> 3, ac = chunk & 7;
        as_off[i] = (uint32_t)(arow * LDA + ac * 8) * 2;
        ag_off[i] = (uint32_t)arow * (D_Z * 2) + ac * 16;
        int brow = chunk >> 4, bc = chunk & 15;
        bs_off[i] = (uint32_t)(brow * LDB + bc * 8) * 2 + A_STAGE_B;
        bg_off[i] = (uint32_t)brow * (D_MODEL * 2) + bc * 16;
    }

    const char* Abase = (const char*)(g_zn + (size_t)(bm * BM) * D_Z);
    const char* Bbase = (const char*)(g_wb + (size_t)(bn * BN));

    // ---- preload stages 0,1 --------------------------------------------
    {
        const char* Ag = Abase;                 // kt=0
        const char* Bg = Bbase;
        #pragma unroll
        for (int i = 0; i < 4; i++) cp_async16(sb + as_off[i], Ag + ag_off[i]);
        #pragma unroll
        for (int i = 0; i < 4; i++) cp_async16(sb + bs_off[i], Bg + bg_off[i]);
        CP_COMMIT();
        Ag += BK * 2;                           // kt=1
        Bg += (size_t)BK * D_MODEL * 2;
        uint32_t s1 = sb + STAGE_B;
        #pragma unroll
        for (int i = 0; i < 4; i++) cp_async16(s1 + as_off[i], Ag + ag_off[i]);
        #pragma unroll
        for (int i = 0; i < 4; i++) cp_async16(s1 + bs_off[i], Bg + bg_off[i]);
        CP_COMMIT();
    }

    // prefetch pointers for stage kt+2
    const char* Agp = Abase + 2 * BK * 2;
    const char* Bgp = Bbase + (size_t)2 * BK * D_MODEL * 2;

    uint32_t abase = sb;                         // rotating stage base
    const uint32_t send = sb + STAGES * STAGE_B;

    uint32_t af0[2][4], af1[2][4];
    uint32_t bfr[2][8];                          // [buf][tile*2 + half]

    for (int kt = 0; kt < KITERS; kt++) {
        CP_WAIT1();
        __syncthreads();

        uint32_t pbase;                          // refill slot base = abase + 2*STAGE_B (mod)
        {
            uint32_t p = abase + 2 * STAGE_B;
            pbase = (p >= send) ? p - STAGES * STAGE_B : p;
        }

        // fragments for ks=0
        ldmatrix_b(bfr[0][0], bfr[0][1], bfr[0][2], bfr[0][3], abase + boff[0]);
        ldmatrix_b(bfr[0][4], bfr[0][5], bfr[0][6], bfr[0][7], abase + boff[1]);
        ldmatrix_x4(af0[0], abase + aoff[0]);
        ldmatrix_x4(af0[1], abase + aoff[1]);

        // refill stage kt+2
        if (kt + 2 < KITERS) {
            #pragma unroll
            for (int i = 0; i < 4; i++) cp_async16(pbase + as_off[i], Agp + ag_off[i]);
            #pragma unroll
            for (int i = 0; i < 4; i++) cp_async16(pbase + bs_off[i], Bgp + bg_off[i]);
            Agp += BK * 2;
            Bgp += (size_t)BK * D_MODEL * 2;
        }
        CP_COMMIT();

        #pragma unroll
        for (int ks = 0; ks < 4; ks++) {
            int cur = ks & 1;
            uint32_t ko2 = (uint32_t)(ks * 16) * 2;
            uint32_t kb1 = (uint32_t)((ks + 1) * 16) * (LDB * 2);

            // A half1 of current ks
            ldmatrix_x4(af1[0], abase + aoff[2] + ko2);
            ldmatrix_x4(af1[1], abase + aoff[3] + ko2);

            // B for ks+1 into alternate buffer (direct write)
            if (ks < 3) {
                ldmatrix_b(bfr[cur ^ 1][0], bfr[cur ^ 1][1], bfr[cur ^ 1][2], bfr[cur ^ 1][3],
                           abase + boff[0] + kb1);
                ldmatrix_b(bfr[cur ^ 1][4], bfr[cur ^ 1][5], bfr[cur ^ 1][6], bfr[cur ^ 1][7],
                           abase + boff[1] + kb1);
            }

            // MMAs half0 (mi 0,1)
            #pragma unroll
            for (int mi = 0; mi < 2; mi++)
                #pragma unroll
                for (int nb = 0; nb < 4; nb++)
                    mma_16816(acc[mi][nb], af0[mi], bfr[cur][nb * 2], bfr[cur][nb * 2 + 1]);

            // A half0 of next ks
            if (ks < 3) {
                ldmatrix_x4(af0[0], abase + aoff[0] + ko2 + 32);
                ldmatrix_x4(af0[1], abase + aoff[1] + ko2 + 32);
            }

            // MMAs half1 (mi 2,3)
            #pragma unroll
            for (int mi = 0; mi < 2; mi++)
                #pragma unroll
                for (int nb = 0; nb < 4; nb++)
                    mma_16816(acc[mi + 2][nb], af1[mi], bfr[cur][nb * 2], bfr[cur][nb * 2 + 1]);
        }

        abase += STAGE_B;
        if (abase >= send) abase = sb;
    }

    // ---- epilogue: out = 3*tanh((acc + bias)*scale/3) ------------------
    float sc3 = scale[0] * (1.0f / 3.0f);
    int rr = lane >> 2;
    int cq = (lane & 3) * 2;

    #pragma unroll
    for (int nb = 0; nb < 4; nb++) {
        int col = bn * BN + wn * 32 + nb * 8 + cq;
        float2 bv = *(const float2*)(bias + col);
        #pragma unroll
        for (int mi = 0; mi < 4; mi++) {
            int row = bm * BM + wm * 64 + mi * 16 + rr;
            float2 o0, o1;
            o0.x = fast_tanh3(acc[mi][nb][0] + bv.x, sc3);
            o0.y = fast_tanh3(acc[mi][nb][1] + bv.y, sc3);
            o1.x = fast_tanh3(acc[mi][nb][2] + bv.x, sc3);
            o1.y = fast_tanh3(acc[mi][nb][3] + bv.y, sc3);
            *(float2*)(out + (size_t)row * D_MODEL + col)       = o0;
            *(float2*)(out + (size_t)(row + 8) * D_MODEL + col) = o1;
        }
    }
}

// ---------------------------------------------------------------- launch
extern "C" void kernel_launch(void* const* d_in, const int* in_sizes, int n_in,
                              void* d_out, int out_size) {
    const float* z     = (const float*)d_in[0];
    const float* gamma = (const float*)d_in[1];
    const float* beta  = (const float*)d_in[2];
    const float* W     = (const float*)d_in[3];
    const float* b     = (const float*)d_in[4];
    const float* scale = (const float*)d_in[5];
    float* out = (float*)d_out;
    (void)in_sizes; (void)n_in; (void)out_size;

    cudaFuncSetAttribute(gemm_kernel, cudaFuncAttributeMaxDynamicSharedMemorySize, SMEM_TOTAL);

    prep_kernel<<<M_ROWS + WCONV_BLOCKS, 256>>>(z, gamma, beta, W);
    dim3 grid(D_MODEL / BN, M_ROWS / BM);   // (32, 128) = 4096 CTAs, 2/SM
    gemm_kernel<<<grid, 256, SMEM_TOTAL>>>(b, scale, out);
}